// round 13
// baseline (speedup 1.0000x reference)
#include <cuda_runtime.h>
#include <cstdint>

#define NB    2
#define NTT   2
#define NLG   256
#define TT    64
#define SS    256
#define NVV   4
#define FF    16
#define KNN   3
#define CUTOFF   1e-3f
#define MASKVAL  1e6f

#define NT_CTA 16          // targets per CTA
#define NTHR   128         // threads per CTA
#define ROWST  288         // dist tile row stride (floats): 8 chunks x 36
#define PENST  264         // penalty row stride (floats)
#define CAP    16          // pool capacity per (t, chunk)
#define PSTR   136         // byte pool stride per t

#define BIGV 3.4e38f
#define BIGI 0x3fffffff

__device__ __forceinline__ bool lessvi(float v, int i, float w, int j) {
    return (v < w) || (v == w && i < j);
}

// exact lexicographic (value, index) top-3 insert
__device__ __forceinline__ void top3_insert_vi(float v, int s,
                                               float& d0, float& d1, float& d2,
                                               int& i0, int& i1, int& i2) {
    if (lessvi(v, s, d2, i2)) {
        if (lessvi(v, s, d1, i1)) {
            d2 = d1; i2 = i1;
            if (lessvi(v, s, d0, i0)) { d1 = d0; i1 = i0; d0 = v; i0 = s; }
            else                      { d1 = v;  i1 = s; }
        } else {
            d2 = v; i2 = s;
        }
    }
}

// s -> chunk-padded dist-tile offset (chunk stride 36 floats)
__device__ __forceinline__ int offS(int s) {
    return (s >> 5) * 36 + (s & 31);
}
// s -> penalty-table offset (pad 4 at s=128)
__device__ __forceinline__ int offP(int s) {
    return s + ((s >> 7) << 2);
}

__global__ __launch_bounds__(NTHR, 9) void interp_kernel(
    const float* __restrict__ x,            // (B,NT, NL*S, NV, F)
    const void*  __restrict__ mask_raw,     // (B,NT, NL*S, NV) — dtype detected
    const float* __restrict__ dist,         // (B, NL, T, S)
    float* __restrict__ out)
{
    __shared__ float         sdist[NT_CTA * ROWST];    // 18.4 KB (swizzled)
    __shared__ float         spen [NVV * PENST];       // 4.2 KB penalty table
    __shared__ unsigned char pool [NT_CTA * PSTR];     // 2.1 KB survivor indices
    __shared__ unsigned char cnts [NT_CTA * 8];        // raw counts
    __shared__ int s_flags[2];

    const int bid   = blockIdx.x;
    const int tb    = bid & 3;               // which 16-target slice of 64
    const int group = bid >> 2;
    const int l     = group & 255;
    const int nt    = (group >> 8) & 1;
    const int b     = group >> 9;
    const int tid   = threadIdx.x;

    if (tid == 0) { s_flags[0] = 0; s_flags[1] = 0; }
    __syncthreads();

    // ---- mask dtype detection from first 1024 bytes ----
    {
        const uchar4* mb = (const uchar4*)mask_raw;
        int u8 = 0, f32 = 0;
        #pragma unroll
        for (int r = 0; r < 2; r++) {
            uchar4 q = mb[tid + r * NTHR];
            u8  |= (q.y == 1) | (q.z == 1) | (q.w == 1);
            f32 |= (q.x == 0x3F) | (q.y == 0x3F) | (q.z == 0x3F) | (q.w == 0x3F);
        }
        if (u8)  atomicOr(&s_flags[0], 1);
        if (f32) atomicOr(&s_flags[1], 1);
    }

    // ---- stage dist tile (16 targets x 256 sources), coalesced, swizzled ----
    {
        const float4* dsrc = (const float4*)(
            dist + (((size_t)(b * NLG + l)) * TT + tb * NT_CTA) * SS);
        #pragma unroll
        for (int i = 0; i < 8; i++) {
            int g = tid + i * NTHR;
            float4 v = dsrc[g];
            int flat = g * 4;
            int t = flat >> 8;                // 0..15
            int s = flat & 255;
            *(float4*)&sdist[t * ROWST + offS(s)] = v;
        }
    }
    __syncthreads();
    const int mkind = s_flags[0] ? 0 : (s_flags[1] ? 2 : 1);

    // ---- stage mask -> penalty table spen[nv][offP(s)] ----
    {
        const size_t moff = ((size_t)((b * NTT + nt) * NLG + l)) * SS * NVV;
        #pragma unroll
        for (int r = 0; r < 2; r++) {
            int s0 = tid + r * NTHR;          // source index 0..255
            float* pb = &spen[offP(s0)];
            if (mkind == 0) {
                const uchar4* msrc = (const uchar4*)((const unsigned char*)mask_raw + moff);
                uchar4 m = msrc[s0];
                pb[0 * PENST] = m.x ? MASKVAL : 0.0f;
                pb[1 * PENST] = m.y ? MASKVAL : 0.0f;
                pb[2 * PENST] = m.z ? MASKVAL : 0.0f;
                pb[3 * PENST] = m.w ? MASKVAL : 0.0f;
            } else if (mkind == 1) {
                const int4* msrc = (const int4*)((const int*)mask_raw + moff);
                int4 m = msrc[s0];
                pb[0 * PENST] = m.x ? MASKVAL : 0.0f;
                pb[1 * PENST] = m.y ? MASKVAL : 0.0f;
                pb[2 * PENST] = m.z ? MASKVAL : 0.0f;
                pb[3 * PENST] = m.w ? MASKVAL : 0.0f;
            } else {
                const float4* msrc = (const float4*)((const float*)mask_raw + moff);
                float4 m = msrc[s0];
                pb[0 * PENST] = m.x * MASKVAL;
                pb[1 * PENST] = m.y * MASKVAL;
                pb[2 * PENST] = m.z * MASKVAL;
                pb[3 * PENST] = m.w * MASKVAL;
            }
        }
    }
    __syncthreads();

    // ============ Phase A: threshold + compaction, one lane per (t,chunk) ==
    // lane owns t = tid>>3 (0..15), chunk c = tid&7; chunk = s in [32c, 32c+32)
    const int at = tid >> 3;
    const int ac = tid & 7;
    const float* cbase = &sdist[at * ROWST + ac * 36];   // this lane's chunk

    // min pass: 8 conflict-free LDS.128, tree-reduced (fma pipe, high ILP)
    float4 f0 = *(const float4*)(cbase + 0);
    float4 f1 = *(const float4*)(cbase + 4);
    float4 f2 = *(const float4*)(cbase + 8);
    float4 f3 = *(const float4*)(cbase + 12);
    float4 f4 = *(const float4*)(cbase + 16);
    float4 f5 = *(const float4*)(cbase + 20);
    float4 f6 = *(const float4*)(cbase + 24);
    float4 f7 = *(const float4*)(cbase + 28);
    float m0 = fminf(fminf(f0.x, f0.y), fminf(f0.z, f0.w));
    float m1 = fminf(fminf(f1.x, f1.y), fminf(f1.z, f1.w));
    float m2 = fminf(fminf(f2.x, f2.y), fminf(f2.z, f2.w));
    float m3 = fminf(fminf(f3.x, f3.y), fminf(f3.z, f3.w));
    float m4 = fminf(fminf(f4.x, f4.y), fminf(f4.z, f4.w));
    float m5 = fminf(fminf(f5.x, f5.y), fminf(f5.z, f5.w));
    float m6 = fminf(fminf(f6.x, f6.y), fminf(f6.z, f6.w));
    float m7 = fminf(fminf(f7.x, f7.y), fminf(f7.z, f7.w));
    float tau = fminf(fminf(fminf(m0, m1), fminf(m2, m3)),
                      fminf(fminf(m4, m5), fminf(m6, m7)));
    tau = fmaxf(tau, __shfl_xor_sync(0xffffffffu, tau, 1));
    tau = fmaxf(tau, __shfl_xor_sync(0xffffffffu, tau, 2));
    tau = fmaxf(tau, __shfl_xor_sync(0xffffffffu, tau, 4));
    // >= 8 candidates of row t are <= tau.

    {   // bitmask compaction: no long predicated-add chain
        #define NIB(F) ((unsigned)((F).x <= tau)       | ((unsigned)((F).y <= tau) << 1) | \
                        ((unsigned)((F).z <= tau) << 2) | ((unsigned)((F).w <= tau) << 3))
        unsigned ma = NIB(f0) | (NIB(f1) << 4);
        unsigned mbt = NIB(f2) | (NIB(f3) << 4);
        unsigned mc = NIB(f4) | (NIB(f5) << 4);
        unsigned md = NIB(f6) | (NIB(f7) << 4);
        unsigned msk = (ma | (mbt << 8)) | ((mc | (md << 8)) << 16);
        #undef NIB
        int cnt = __popc(msk);
        unsigned char* mypool = &pool[at * PSTR + ac * CAP];
        int k = 0;
        int sbase = ac * 32;
        while (msk && k < CAP) {
            int j = __ffs(msk) - 1;
            msk &= msk - 1;
            mypool[k++] = (unsigned char)(sbase + j);
        }
        cnts[at * 8 + ac] = (unsigned char)cnt;
    }
    __syncthreads();

    // ============ Phase B: exact top-3 over the pool, dual accumulators ====
    const int nv = tid & 3;
    const int ph = (tid >> 2) & 1;
    const int t  = tid >> 3;                  // == at, tau valid for this t
    const float* dt = &sdist[t * ROWST];
    const float* pn = &spen[nv * PENST];

    float a0 = BIGV, a1 = BIGV, a2 = BIGV;
    int   ai0 = BIGI, ai1 = BIGI, ai2 = BIGI;
    float b0 = BIGV, b1 = BIGV, b2 = BIGV;
    int   bi0 = BIGI, bi1 = BIGI, bi2 = BIGI;
    int ovf = 0;

    #pragma unroll
    for (int c = 0; c < 8; c += 2) {
        // even chunk -> accumulator A
        {
            int n = cnts[t * 8 + c];
            if (n > CAP) { ovf = 1; n = CAP; }
            const unsigned char* pp = &pool[t * PSTR + c * CAP];
            for (int i = ph; i < n; i += 2) {
                int s = pp[i];
                float v = dt[offS(s)] + pn[offP(s)];
                top3_insert_vi(v, s, a0, a1, a2, ai0, ai1, ai2);
            }
        }
        // odd chunk -> accumulator B (independent chain)
        {
            int n = cnts[t * 8 + c + 1];
            if (n > CAP) { ovf = 1; n = CAP; }
            const unsigned char* pp = &pool[t * PSTR + (c + 1) * CAP];
            for (int i = ph; i < n; i += 2) {
                int s = pp[i];
                float v = dt[offS(s)] + pn[offP(s)];
                top3_insert_vi(v, s, b0, b1, b2, bi0, bi1, bi2);
            }
        }
    }
    // merge B into A (lexicographic, exact)
    top3_insert_vi(b0, bi0, a0, a1, a2, ai0, ai1, ai2);
    top3_insert_vi(b1, bi1, a0, a1, a2, ai0, ai1, ai2);
    top3_insert_vi(b2, bi2, a0, a1, a2, ai0, ai1, ai2);

    // merge the two ph lanes (partner = lane ^ 4) — shfls unconditional
    {
        float ov0 = __shfl_xor_sync(0xffffffffu, a0, 4);
        float ov1 = __shfl_xor_sync(0xffffffffu, a1, 4);
        float ov2 = __shfl_xor_sync(0xffffffffu, a2, 4);
        int   oi0 = __shfl_xor_sync(0xffffffffu, ai0, 4);
        int   oi1 = __shfl_xor_sync(0xffffffffu, ai1, 4);
        int   oi2 = __shfl_xor_sync(0xffffffffu, ai2, 4);
        top3_insert_vi(ov0, oi0, a0, a1, a2, ai0, ai1, ai2);
        top3_insert_vi(ov1, oi1, a0, a1, a2, ai0, ai1, ai2);
        top3_insert_vi(ov2, oi2, a0, a1, a2, ai0, ai1, ai2);
    }
    int ovf_other = __shfl_xor_sync(0xffffffffu, ovf, 4);   // never short-circuit a shfl
    ovf |= ovf_other;

    // exactness: excluded unmasked sources have dist > tau; masked pooled
    // entries carry +1e6 > tau. a2 <= tau and no overflow => exact.
    bool flag = (ovf != 0) || (a2 > tau);
    if (__any_sync(0xffffffffu, flag)) {
        float g0v = BIGV, g1v = BIGV, g2v = BIGV;
        int   g0 = BIGI, g1 = BIGI, g2 = BIGI;
        for (int k = 0; k < 128; k++) {
            int s = (k << 1) | ph;
            float v = dt[offS(s)] + pn[offP(s)];
            top3_insert_vi(v, s, g0v, g1v, g2v, g0, g1, g2);
        }
        float ov0 = __shfl_xor_sync(0xffffffffu, g0v, 4);
        float ov1 = __shfl_xor_sync(0xffffffffu, g1v, 4);
        float ov2 = __shfl_xor_sync(0xffffffffu, g2v, 4);
        int   oi0 = __shfl_xor_sync(0xffffffffu, g0, 4);
        int   oi1 = __shfl_xor_sync(0xffffffffu, g1, 4);
        int   oi2 = __shfl_xor_sync(0xffffffffu, g2, 4);
        top3_insert_vi(ov0, oi0, g0v, g1v, g2v, g0, g1, g2);
        top3_insert_vi(ov1, oi1, g0v, g1v, g2v, g0, g1, g2);
        top3_insert_vi(ov2, oi2, g0v, g1v, g2v, g0, g1, g2);
        if (flag) {
            a0 = g0v; a1 = g1v; a2 = g2v;
            ai0 = g0; ai1 = g1; ai2 = g2;
        }
    }

    // ---- weights ----
    float c0 = fmaxf(a0, CUTOFF);
    float c1 = fmaxf(a1, CUTOFF);
    float c2 = fmaxf(a2, CUTOFF);
    float w0 = 1.0f / (c0 * c0);
    float w1 = 1.0f / (c1 * c1);
    float w2 = 1.0f / (c2 * c2);
    float inv = 1.0f / (w0 + w1 + w2);
    w0 *= inv; w1 *= inv; w2 *= inv;

    // ---- gather + blend: each ph lane writes 2 of the 4 float4s ----
    const int tg = t + tb * NT_CTA;            // global target 0..63
    const float* xb = x + ((size_t)((b * NTT + nt) * NLG + l)) * SS * NVV * FF;
    const float4* xp0 = (const float4*)(xb + ((size_t)ai0 * NVV + nv) * FF);
    const float4* xp1 = (const float4*)(xb + ((size_t)ai1 * NVV + nv) * FF);
    const float4* xp2 = (const float4*)(xb + ((size_t)ai2 * NVV + nv) * FF);

    const size_t row = (size_t)((b * NTT + nt) * (NLG * TT)) + (size_t)l * TT + tg;
    float4* op = (float4*)(out + (row * NVV + nv) * FF);

    const int j0 = ph * 2;
    #pragma unroll
    for (int j = j0; j < j0 + 2; j++) {
        float4 va = xp0[j], vb = xp1[j], vc = xp2[j];
        float4 rr;
        rr.x = w0 * va.x + w1 * vb.x + w2 * vc.x;
        rr.y = w0 * va.y + w1 * vb.y + w2 * vc.y;
        rr.z = w0 * va.z + w1 * vb.z + w2 * vc.z;
        rr.w = w0 * va.w + w1 * vb.w + w2 * vc.w;
        op[j] = rr;
    }

    // ---- dist_vals output: split between the two ph lanes ----
    const size_t XSZ = (size_t)NB * NTT * NLG * TT * NVV * FF;  // 4,194,304
    size_t dbaseo = XSZ + (row * KNN) * NVV + nv;
    if (ph == 0) {
        out[dbaseo]       = c0;
        out[dbaseo + NVV] = c1;
    } else {
        out[dbaseo + 2 * NVV] = c2;
    }
}

extern "C" void kernel_launch(void* const* d_in, const int* in_sizes, int n_in,
                              void* d_out, int out_size) {
    const float* x    = (const float*)d_in[0];
    const void*  mask = (const void*)d_in[1];
    const float* dist = (const float*)d_in[2];
    float*       out  = (float*)d_out;

    interp_kernel<<<NB * NTT * NLG * 4, NTHR>>>(x, mask, dist, out);
}

// round 14
// speedup vs baseline: 1.3026x; 1.3026x over previous
#include <cuda_runtime.h>
#include <cstdint>

#define NB    2
#define NTT   2
#define NLG   256
#define TT    64
#define SS    256
#define NVV   4
#define FF    16
#define KNN   3
#define CUTOFF   1e-3f
#define MASKVAL  1e6f

#define NT_CTA 16          // targets per CTA
#define NTHR   128         // threads per CTA
#define ROWST  264         // row stride (floats) for dist tile AND penalty tables
#define CAP    16          // pool capacity per (t, chunk)
#define PSTR   136         // byte pool stride per t

#define BIGV 3.4e38f
#define BIGI 0x3fffffff

__device__ __forceinline__ bool lessvi(float v, int i, float w, int j) {
    return (v < w) || (v == w && i < j);
}

// exact lexicographic (value, index) top-3 insert
__device__ __forceinline__ void top3_insert_vi(float v, int s,
                                               float& d0, float& d1, float& d2,
                                               int& i0, int& i1, int& i2) {
    if (lessvi(v, s, d2, i2)) {
        if (lessvi(v, s, d1, i1)) {
            d2 = d1; i2 = i1;
            if (lessvi(v, s, d0, i0)) { d1 = d0; i1 = i0; d0 = v; i0 = s; }
            else                      { d1 = v;  i1 = s; }
        } else {
            d2 = v; i2 = s;
        }
    }
}

__device__ __forceinline__ int offmap(int s) {  // s -> padded offset
    return s + ((s >> 7) << 2);                 // s<128: s ; s>=128: s+4
}

__global__ __launch_bounds__(NTHR, 8) void interp_kernel(
    const float* __restrict__ x,            // (B,NT, NL*S, NV, F)
    const void*  __restrict__ mask_raw,     // (B,NT, NL*S, NV) — dtype detected
    const float* __restrict__ dist,         // (B, NL, T, S)
    float* __restrict__ out)
{
    __shared__ float         sdist[NT_CTA * ROWST];    // 16.9 KB, shared by both nt
    __shared__ float         spen [2 * NVV * ROWST];   // 8.4 KB: [nt*4+nv][offmap(s)]
    __shared__ unsigned char pool [NT_CTA * PSTR];     // 2.1 KB survivor indices
    __shared__ unsigned char cnts [NT_CTA * 8];        // raw counts
    __shared__ int s_flags[2];

    const int bid   = blockIdx.x;
    const int tb    = bid & 3;               // which 16-target slice of 64
    const int group = bid >> 2;
    const int l     = group & 255;
    const int b     = group >> 8;            // 0..1   (no nt in bid!)
    const int tid   = threadIdx.x;

    if (tid == 0) { s_flags[0] = 0; s_flags[1] = 0; }
    __syncthreads();

    // ---- mask dtype detection from first 1024 bytes ----
    {
        const uchar4* mb = (const uchar4*)mask_raw;
        int u8 = 0, f32 = 0;
        #pragma unroll
        for (int r = 0; r < 2; r++) {
            uchar4 q = mb[tid + r * NTHR];
            u8  |= (q.y == 1) | (q.z == 1) | (q.w == 1);
            f32 |= (q.x == 0x3F) | (q.y == 0x3F) | (q.z == 0x3F) | (q.w == 0x3F);
        }
        if (u8)  atomicOr(&s_flags[0], 1);
        if (f32) atomicOr(&s_flags[1], 1);
    }

    // ---- stage dist tile (16 targets x 256 sources) ONCE for both nt ----
    {
        const float4* dsrc = (const float4*)(
            dist + (((size_t)(b * NLG + l)) * TT + tb * NT_CTA) * SS);
        #pragma unroll
        for (int i = 0; i < 8; i++) {
            int g = tid + i * NTHR;
            float4 v = dsrc[g];
            int flat = g * 4;
            int t = flat >> 8;                // 0..15
            int s = flat & 255;
            *(float4*)&sdist[t * ROWST + offmap(s)] = v;
        }
    }
    __syncthreads();
    const int mkind = s_flags[0] ? 0 : (s_flags[1] ? 2 : 1);

    // ---- stage BOTH penalty tables: spen[nt*4+nv][offmap(s)] ----
    #pragma unroll
    for (int nti = 0; nti < 2; nti++) {
        const size_t moff = ((size_t)((b * NTT + nti) * NLG + l)) * SS * NVV;
        #pragma unroll
        for (int r = 0; r < 2; r++) {
            int s0 = tid + r * NTHR;          // source index 0..255
            float* pb = &spen[(nti * NVV) * ROWST + offmap(s0)];
            if (mkind == 0) {
                const uchar4* msrc = (const uchar4*)((const unsigned char*)mask_raw + moff);
                uchar4 m = msrc[s0];
                pb[0 * ROWST] = m.x ? MASKVAL : 0.0f;
                pb[1 * ROWST] = m.y ? MASKVAL : 0.0f;
                pb[2 * ROWST] = m.z ? MASKVAL : 0.0f;
                pb[3 * ROWST] = m.w ? MASKVAL : 0.0f;
            } else if (mkind == 1) {
                const int4* msrc = (const int4*)((const int*)mask_raw + moff);
                int4 m = msrc[s0];
                pb[0 * ROWST] = m.x ? MASKVAL : 0.0f;
                pb[1 * ROWST] = m.y ? MASKVAL : 0.0f;
                pb[2 * ROWST] = m.z ? MASKVAL : 0.0f;
                pb[3 * ROWST] = m.w ? MASKVAL : 0.0f;
            } else {
                const float4* msrc = (const float4*)((const float*)mask_raw + moff);
                float4 m = msrc[s0];
                pb[0 * ROWST] = m.x * MASKVAL;
                pb[1 * ROWST] = m.y * MASKVAL;
                pb[2 * ROWST] = m.z * MASKVAL;
                pb[3 * ROWST] = m.w * MASKVAL;
            }
        }
    }
    __syncthreads();

    // ============ Phase A (ONCE, nt-independent): threshold + compaction ===
    // lane owns t = tid>>3 (0..15), chunk c = tid&7; chunk covers s = c + 8j.
    const int at = tid >> 3;
    const int ac = tid & 7;
    const float* dbt = &sdist[at * ROWST];

    float q0 = BIGV, q1 = BIGV, q2 = BIGV, q3 = BIGV;
    #pragma unroll
    for (int j = 0; j < 16; j += 4) {          // s < 128
        q0 = fminf(q0, dbt[ac + 8 * (j + 0)]);
        q1 = fminf(q1, dbt[ac + 8 * (j + 1)]);
        q2 = fminf(q2, dbt[ac + 8 * (j + 2)]);
        q3 = fminf(q3, dbt[ac + 8 * (j + 3)]);
    }
    #pragma unroll
    for (int j = 16; j < 32; j += 4) {         // s >= 128 (+4 pad)
        q0 = fminf(q0, dbt[ac + 8 * (j + 0) + 4]);
        q1 = fminf(q1, dbt[ac + 8 * (j + 1) + 4]);
        q2 = fminf(q2, dbt[ac + 8 * (j + 2) + 4]);
        q3 = fminf(q3, dbt[ac + 8 * (j + 3) + 4]);
    }
    float tau = fminf(fminf(q0, q1), fminf(q2, q3));
    tau = fmaxf(tau, __shfl_xor_sync(0xffffffffu, tau, 1));
    tau = fmaxf(tau, __shfl_xor_sync(0xffffffffu, tau, 2));
    tau = fmaxf(tau, __shfl_xor_sync(0xffffffffu, tau, 4));
    // >= 8 candidates of row t are <= tau.

    {   // compaction of survivor indices into the byte pool
        unsigned char* mypool = &pool[at * PSTR + ac * CAP];
        int cnt = 0;
        #pragma unroll
        for (int j = 0; j < 16; j++) {
            int s = ac + 8 * j;
            if (dbt[s] <= tau) { if (cnt < CAP) mypool[cnt] = (unsigned char)s; cnt++; }
        }
        #pragma unroll
        for (int j = 16; j < 32; j++) {
            int s = ac + 8 * j;
            if (dbt[s + 4] <= tau) { if (cnt < CAP) mypool[cnt] = (unsigned char)s; cnt++; }
        }
        cnts[at * 8 + ac] = (unsigned char)cnt;
    }
    __syncthreads();

    // ============ Phase B: exact top-3 for BOTH nt over the shared pool ====
    const int nv = tid & 3;
    const int ph = (tid >> 2) & 1;
    const int t  = tid >> 3;                  // == at, tau valid for this t
    const float* dt  = &sdist[t * ROWST];
    const float* pn0 = &spen[nv * ROWST];
    const float* pn1 = &spen[(NVV + nv) * ROWST];

    float a0 = BIGV, a1 = BIGV, a2 = BIGV;    // nt = 0
    int   ai0 = BIGI, ai1 = BIGI, ai2 = BIGI;
    float e0 = BIGV, e1 = BIGV, e2 = BIGV;    // nt = 1
    int   ei0 = BIGI, ei1 = BIGI, ei2 = BIGI;
    int ovf = 0;

    #pragma unroll
    for (int c = 0; c < 8; c++) {
        int n = cnts[t * 8 + c];
        if (n > CAP) { ovf = 1; n = CAP; }
        const unsigned char* pp = &pool[t * PSTR + c * CAP];
        for (int i = ph; i < n; i += 2) {
            int s = pp[i];
            int off = offmap(s);
            float d = dt[off];                 // shared load for both nt
            top3_insert_vi(d + pn0[off], s, a0, a1, a2, ai0, ai1, ai2);
            top3_insert_vi(d + pn1[off], s, e0, e1, e2, ei0, ei1, ei2);
        }
    }

    // merge the two ph lanes (partner = lane ^ 4) — shfls unconditional
    {
        float ov0 = __shfl_xor_sync(0xffffffffu, a0, 4);
        float ov1 = __shfl_xor_sync(0xffffffffu, a1, 4);
        float ov2 = __shfl_xor_sync(0xffffffffu, a2, 4);
        int   oi0 = __shfl_xor_sync(0xffffffffu, ai0, 4);
        int   oi1 = __shfl_xor_sync(0xffffffffu, ai1, 4);
        int   oi2 = __shfl_xor_sync(0xffffffffu, ai2, 4);
        top3_insert_vi(ov0, oi0, a0, a1, a2, ai0, ai1, ai2);
        top3_insert_vi(ov1, oi1, a0, a1, a2, ai0, ai1, ai2);
        top3_insert_vi(ov2, oi2, a0, a1, a2, ai0, ai1, ai2);
    }
    {
        float ov0 = __shfl_xor_sync(0xffffffffu, e0, 4);
        float ov1 = __shfl_xor_sync(0xffffffffu, e1, 4);
        float ov2 = __shfl_xor_sync(0xffffffffu, e2, 4);
        int   oi0 = __shfl_xor_sync(0xffffffffu, ei0, 4);
        int   oi1 = __shfl_xor_sync(0xffffffffu, ei1, 4);
        int   oi2 = __shfl_xor_sync(0xffffffffu, ei2, 4);
        top3_insert_vi(ov0, oi0, e0, e1, e2, ei0, ei1, ei2);
        top3_insert_vi(ov1, oi1, e0, e1, e2, ei0, ei1, ei2);
        top3_insert_vi(ov2, oi2, e0, e1, e2, ei0, ei1, ei2);
    }
    int ovf_other = __shfl_xor_sync(0xffffffffu, ovf, 4);   // never short-circuit a shfl
    ovf |= ovf_other;

    // exactness per nt: excluded unmasked sources have dist > tau; masked pooled
    // entries carry +1e6 > tau. aX2 <= tau and no overflow => exact.
    bool flag0 = (ovf != 0) || (a2 > tau);
    bool flag1 = (ovf != 0) || (e2 > tau);
    if (__any_sync(0xffffffffu, flag0 || flag1)) {
        float f0 = BIGV, f1 = BIGV, f2 = BIGV;   // nt=0 fallback
        int   g0 = BIGI, g1 = BIGI, g2 = BIGI;
        float h0 = BIGV, h1 = BIGV, h2 = BIGV;   // nt=1 fallback
        int   k0 = BIGI, k1 = BIGI, k2 = BIGI;
        for (int k = 0; k < 128; k++) {
            int s = (k << 1) | ph;
            int off = offmap(s);
            float d = dt[off];
            top3_insert_vi(d + pn0[off], s, f0, f1, f2, g0, g1, g2);
            top3_insert_vi(d + pn1[off], s, h0, h1, h2, k0, k1, k2);
        }
        {
            float ov0 = __shfl_xor_sync(0xffffffffu, f0, 4);
            float ov1 = __shfl_xor_sync(0xffffffffu, f1, 4);
            float ov2 = __shfl_xor_sync(0xffffffffu, f2, 4);
            int   oi0 = __shfl_xor_sync(0xffffffffu, g0, 4);
            int   oi1 = __shfl_xor_sync(0xffffffffu, g1, 4);
            int   oi2 = __shfl_xor_sync(0xffffffffu, g2, 4);
            top3_insert_vi(ov0, oi0, f0, f1, f2, g0, g1, g2);
            top3_insert_vi(ov1, oi1, f0, f1, f2, g0, g1, g2);
            top3_insert_vi(ov2, oi2, f0, f1, f2, g0, g1, g2);
        }
        {
            float ov0 = __shfl_xor_sync(0xffffffffu, h0, 4);
            float ov1 = __shfl_xor_sync(0xffffffffu, h1, 4);
            float ov2 = __shfl_xor_sync(0xffffffffu, h2, 4);
            int   oi0 = __shfl_xor_sync(0xffffffffu, k0, 4);
            int   oi1 = __shfl_xor_sync(0xffffffffu, k1, 4);
            int   oi2 = __shfl_xor_sync(0xffffffffu, k2, 4);
            top3_insert_vi(ov0, oi0, h0, h1, h2, k0, k1, k2);
            top3_insert_vi(ov1, oi1, h0, h1, h2, k0, k1, k2);
            top3_insert_vi(ov2, oi2, h0, h1, h2, k0, k1, k2);
        }
        if (flag0) { a0 = f0; a1 = f1; a2 = f2; ai0 = g0; ai1 = g1; ai2 = g2; }
        if (flag1) { e0 = h0; e1 = h1; e2 = h2; ei0 = k0; ei1 = k1; ei2 = k2; }
    }

    // ---- epilogue per nt ----
    const int tg = t + tb * NT_CTA;            // global target 0..63
    const size_t XSZ = (size_t)NB * NTT * NLG * TT * NVV * FF;  // 4,194,304
    const int j0 = ph * 2;

    #pragma unroll
    for (int nti = 0; nti < 2; nti++) {
        float r0, r1, r2; int s0, s1, s2;
        if (nti == 0) { r0 = a0; r1 = a1; r2 = a2; s0 = ai0; s1 = ai1; s2 = ai2; }
        else          { r0 = e0; r1 = e1; r2 = e2; s0 = ei0; s1 = ei1; s2 = ei2; }

        float c0 = fmaxf(r0, CUTOFF);
        float c1 = fmaxf(r1, CUTOFF);
        float c2 = fmaxf(r2, CUTOFF);
        float w0 = 1.0f / (c0 * c0);
        float w1 = 1.0f / (c1 * c1);
        float w2 = 1.0f / (c2 * c2);
        float inv = 1.0f / (w0 + w1 + w2);
        w0 *= inv; w1 *= inv; w2 *= inv;

        const float* xb = x + ((size_t)((b * NTT + nti) * NLG + l)) * SS * NVV * FF;
        const float4* xp0 = (const float4*)(xb + ((size_t)s0 * NVV + nv) * FF);
        const float4* xp1 = (const float4*)(xb + ((size_t)s1 * NVV + nv) * FF);
        const float4* xp2 = (const float4*)(xb + ((size_t)s2 * NVV + nv) * FF);

        const size_t row = (size_t)((b * NTT + nti) * (NLG * TT)) + (size_t)l * TT + tg;
        float4* op = (float4*)(out + (row * NVV + nv) * FF);

        #pragma unroll
        for (int j = j0; j < j0 + 2; j++) {
            float4 va = xp0[j], vb = xp1[j], vc = xp2[j];
            float4 rr;
            rr.x = w0 * va.x + w1 * vb.x + w2 * vc.x;
            rr.y = w0 * va.y + w1 * vb.y + w2 * vc.y;
            rr.z = w0 * va.z + w1 * vb.z + w2 * vc.z;
            rr.w = w0 * va.w + w1 * vb.w + w2 * vc.w;
            op[j] = rr;
        }

        size_t dbaseo = XSZ + (row * KNN) * NVV + nv;
        if (ph == 0) {
            out[dbaseo]       = c0;
            out[dbaseo + NVV] = c1;
        } else {
            out[dbaseo + 2 * NVV] = c2;
        }
    }
}

extern "C" void kernel_launch(void* const* d_in, const int* in_sizes, int n_in,
                              void* d_out, int out_size) {
    const float* x    = (const float*)d_in[0];
    const void*  mask = (const void*)d_in[1];
    const float* dist = (const float*)d_in[2];
    float*       out  = (float*)d_out;

    interp_kernel<<<NB * NLG * 4, NTHR>>>(x, mask, dist, out);
}